// round 14
// baseline (speedup 1.0000x reference)
#include <cuda_runtime.h>
#include <cuda_bf16.h>
#include <cstdint>

// Problem constants
#define N_PTS 262144
#define D     128
#define D4    32
#define K     512
#define NITER 5
#define NTILE (N_PTS / 128)

#define BP        128
#define NCHUNKS   8
#define KSUB      2
#define NTHREADS  288     // warps 0-7 epilogue, warp 8 driver

// SMEM layout
#define A_SPLIT_BYTES  32768
#define A_TOTAL        (3 * A_SPLIT_BYTES)            // 98304
#define B_SPLIT_BYTES  16384
#define B_SLOT_BYTES   (3 * B_SPLIT_BYTES)            // 49152
#define B_TOTAL        (2 * B_SLOT_BYTES)             // 98304
#define SMEM_DYN_BYTES (3072 + A_TOTAL + B_TOTAL)     // 199680

#define A_TILE_U32  24576
#define B_IMG_U32   98304

// bf16 MMA idesc: dtype=F32, a=BF16, b=BF16, N=64, M=128
#define MMA_IDESC 0x08100490u
#define SMEM_DESC_BASE 0x4000404000010000ULL
#define SW128(o) ((o) ^ ((((unsigned)(o)) >> 3) & 0x70u))

#if defined(__CUDA_ARCH__) && (defined(__CUDA_ARCH_FEAT_SM103_ALL) || \
                               defined(__CUDA_ARCH_FEAT_SM100_ALL) || \
                               defined(__CUDA_ARCH_FEAT_SM101_ALL))
#define HAVE_TCGEN05 1
#else
#define HAVE_TCGEN05 0
#endif

// Scratch state
__device__ float    g_cent[K * D];
__device__ float    g_sums[K * D];
__device__ float    g_counts[K];
__device__ int      g_assign[N_PTS];
__device__ __align__(128) unsigned g_embA[NTILE * A_TILE_U32];
__device__ __align__(128) unsigned g_centB[B_IMG_U32];

// ---------------------------------------------------------------------------
__device__ __forceinline__ unsigned smem_u32(const void* p) {
    unsigned a;
    asm("{ .reg .u64 t; cvta.to.shared.u64 t, %1; cvt.u32.u64 %0, t; }"
        : "=r"(a) : "l"(p));
    return a;
}

#define MBARRIER_INIT(a, c) \
    asm volatile("mbarrier.init.shared.b64 [%0], %1;" :: "r"(a), "r"(c) : "memory")
#define MBARRIER_INVAL(a) \
    asm volatile("mbarrier.inval.shared.b64 [%0];" :: "r"(a) : "memory")
#define MBARRIER_EXPECT_TX(a, b) \
    asm volatile("mbarrier.arrive.expect_tx.shared.b64 _, [%0], %1;" \
                 :: "r"(a), "r"(b) : "memory")

#define MBARRIER_WAIT_PARITY(mbar, parity) do { \
    unsigned _m = (mbar), _p = (parity), _d; \
    asm volatile("{\n\t.reg .pred p;\n\t" \
        "mbarrier.try_wait.parity.acquire.cta.shared::cta.b64 p, [%1], %2;\n\t" \
        "selp.b32 %0, 1, 0, p;\n\t}" : "=r"(_d) : "r"(_m), "r"(_p) : "memory"); \
    if (!_d) { \
        asm volatile("{\n\t.reg .pred P1;\n\t" \
            "WL_%=:\n\t" \
            "mbarrier.try_wait.parity.acquire.cta.shared::cta.b64 P1, [%0], %1, 0x989680;\n\t" \
            "@P1 bra.uni WD_%=;\n\tbra.uni WL_%=;\n\tWD_%=:\n\t}" \
            :: "r"(_m), "r"(_p) : "memory"); \
    } \
} while (0)

#define BULK_G2S(dst, src, bytes, mbar) \
    asm volatile("cp.async.bulk.shared::cta.global.mbarrier::complete_tx::bytes " \
                 "[%0], [%1], %2, [%3];" \
                 :: "r"(dst), "l"(src), "r"(bytes), "r"(mbar) : "memory")

#if HAVE_TCGEN05
#define TCGEN05_ALLOC(sa, n) \
    asm volatile("tcgen05.alloc.cta_group::1.sync.aligned.shared::cta.b32 [%0], %1;" \
                 :: "r"(sa), "r"(n) : "memory")
#define TCGEN05_DEALLOC(t, n) \
    asm volatile("tcgen05.dealloc.cta_group::1.sync.aligned.b32 %0, %1;" :: "r"(t), "r"(n))
#define TCGEN05_RELINQUISH() \
    asm volatile("tcgen05.relinquish_alloc_permit.cta_group::1.sync.aligned;")
#define TCGEN05_COMMIT(m) \
    asm volatile("tcgen05.commit.cta_group::1.mbarrier::arrive::one.shared::cluster.b64 [%0];" \
                 :: "r"(m) : "memory")
#define TCGEN05_FENCE_BEFORE() asm volatile("tcgen05.fence::before_thread_sync;" ::: "memory")
#define TCGEN05_FENCE_AFTER()  asm volatile("tcgen05.fence::after_thread_sync;"  ::: "memory")
#define TCGEN05_WAIT_LD()      asm volatile("tcgen05.wait::ld.sync.aligned;" ::: "memory")

#define TCGEN05_LD_32X32B_X32(r, tmem_addr) \
    asm volatile( \
        "tcgen05.ld.sync.aligned.32x32b.x32.b32 " \
        "{%0, %1, %2, %3, %4, %5, %6, %7, " \
        " %8, %9, %10, %11, %12, %13, %14, %15, " \
        " %16, %17, %18, %19, %20, %21, %22, %23, " \
        " %24, %25, %26, %27, %28, %29, %30, %31}, [%32];" \
        : "=r"((r)[0]),  "=r"((r)[1]),  "=r"((r)[2]),  "=r"((r)[3]), \
          "=r"((r)[4]),  "=r"((r)[5]),  "=r"((r)[6]),  "=r"((r)[7]), \
          "=r"((r)[8]),  "=r"((r)[9]),  "=r"((r)[10]), "=r"((r)[11]), \
          "=r"((r)[12]), "=r"((r)[13]), "=r"((r)[14]), "=r"((r)[15]), \
          "=r"((r)[16]), "=r"((r)[17]), "=r"((r)[18]), "=r"((r)[19]), \
          "=r"((r)[20]), "=r"((r)[21]), "=r"((r)[22]), "=r"((r)[23]), \
          "=r"((r)[24]), "=r"((r)[25]), "=r"((r)[26]), "=r"((r)[27]), \
          "=r"((r)[28]), "=r"((r)[29]), "=r"((r)[30]), "=r"((r)[31]) \
        : "r"(tmem_addr))

__device__ __forceinline__ void mma_bf16_ss(unsigned d_tmem, unsigned long long a_desc,
                                            unsigned long long b_desc, unsigned en) {
    asm volatile(
        "{\n\t.reg .pred p;\n\tsetp.ne.u32 p, %4, 0;\n\t"
        "tcgen05.mma.cta_group::1.kind::f16 [%0], %1, %2, %3, {%5, %5, %5, %5}, p;\n\t}"
        :: "r"(d_tmem), "l"(a_desc), "l"(b_desc), "r"(MMA_IDESC), "r"(en), "r"(0u)
        : "memory");
}
#endif  // HAVE_TCGEN05

__device__ __forceinline__ unsigned long long mk_desc(unsigned byte_addr) {
    return SMEM_DESC_BASE | (unsigned long long)((byte_addr >> 4) & 0x3FFFu);
}

__device__ __forceinline__ void split3_pack(float x, float y,
                                            unsigned& ph, unsigned& pl, unsigned& pr) {
    __nv_bfloat16 xh = __float2bfloat16_rn(x);
    float xr1 = x - __bfloat162float(xh);
    __nv_bfloat16 xl = __float2bfloat16_rn(xr1);
    __nv_bfloat16 xr = __float2bfloat16_rn(xr1 - __bfloat162float(xl));
    __nv_bfloat16 yh = __float2bfloat16_rn(y);
    float yr1 = y - __bfloat162float(yh);
    __nv_bfloat16 yl = __float2bfloat16_rn(yr1);
    __nv_bfloat16 yr = __float2bfloat16_rn(yr1 - __bfloat162float(yl));
    ph = (unsigned)__bfloat16_as_ushort(xh) | ((unsigned)__bfloat16_as_ushort(yh) << 16);
    pl = (unsigned)__bfloat16_as_ushort(xl) | ((unsigned)__bfloat16_as_ushort(yl) << 16);
    pr = (unsigned)__bfloat16_as_ushort(xr) | ((unsigned)__bfloat16_as_ushort(yr) << 16);
}

__device__ __forceinline__ unsigned f2sortable(float f) {
    unsigned u = __float_as_uint(f);
    return u ^ (((int)u >> 31) | 0x80000000u);
}

// ---------------------------------------------------------------------------
__global__ void init_kernel(const float* __restrict__ initc) {
    int i = blockIdx.x * blockDim.x + threadIdx.x;
    if (i < K * D) { g_cent[i] = initc[i]; g_sums[i] = 0.0f; }
    if (i < K)     g_counts[i] = 0.0f;
}

// ---------------------------------------------------------------------------
// Once per launch: pack embedding 3-way bf16 splits into swizzled tile images.
// ---------------------------------------------------------------------------
__global__ void emb_split_kernel(const float4* __restrict__ emb) {
    const int tile = blockIdx.x;
    const int w    = threadIdx.x >> 5;
    const int lane = threadIdx.x & 31;
    unsigned* out = g_embA + (size_t)tile * A_TILE_U32;
    const unsigned subbase = (unsigned)(lane >> 4) * 4096u;
    for (int r = w; r < 128; r += 8) {
        float4 v = emb[(size_t)(tile * 128 + r) * D4 + lane];
        unsigned off = (unsigned)(r * 128 + 8 * (lane & 15));
        unsigned s0 = SW128(off) >> 2, s1 = SW128(off + 4) >> 2;
        unsigned ph, pl, pr, qh, ql, qr;
        split3_pack(v.x, v.y, ph, pl, pr);
        split3_pack(v.z, v.w, qh, ql, qr);
        out[subbase + s0]          = ph;  out[subbase + s1]          = qh;
        out[8192u + subbase + s0]  = pl;  out[8192u + subbase + s1]  = ql;
        out[16384u + subbase + s0] = pr;  out[16384u + subbase + s1] = qr;
    }
}

// ---------------------------------------------------------------------------
// Run ONCE before the loop: pack init centroid splits into swizzled image.
// (Subsequent images come from update_kernel.)
// ---------------------------------------------------------------------------
__global__ void cent_split_kernel() {
    const int gw   = (blockIdx.x * blockDim.x + threadIdx.x) >> 5;
    const int lane = threadIdx.x & 31;
    if (gw >= K) return;
    float4 v = ((const float4*)g_cent)[(size_t)gw * D4 + lane];
    const unsigned subbase = (unsigned)(lane >> 4) * 16384u;
    unsigned off = (unsigned)(gw * 128 + 8 * (lane & 15));
    unsigned s0 = SW128(off) >> 2, s1 = SW128(off + 4) >> 2;
    unsigned ph, pl, pr, qh, ql, qr;
    split3_pack(v.x, v.y, ph, pl, pr);
    split3_pack(v.z, v.w, qh, ql, qr);
    g_centB[subbase + s0]           = ph;  g_centB[subbase + s1]           = qh;
    g_centB[32768u + subbase + s0]  = pl;  g_centB[32768u + subbase + s1]  = ql;
    g_centB[65536u + subbase + s0]  = pr;  g_centB[65536u + subbase + s1]  = qr;
}

// ---------------------------------------------------------------------------
// E-step, sm_103a: identical compute/sync structure to the passing round-12
// kernel (SS tcgen05, single accumulator, smalls-first, 8 single-use commit
// barriers, warp-8 driver, per-chunk-group overlapped epilogue), PLUS a fused
// M-step accumulate tail: after the argmax combine, the 9 warps red.add this
// tile's 128 embedding rows into g_sums/g_counts (replaces accum_kernel).
// ---------------------------------------------------------------------------
__global__ void __launch_bounds__(NTHREADS, 1)
assign_tc_kernel(const float4* __restrict__ emb) {
#if HAVE_TCGEN05
    extern __shared__ char smem[];
    const unsigned smem_base = smem_u32(smem);
    const unsigned tiles = (smem_base + 2048u + 1023u) & ~1023u;
    const unsigned a_base = tiles;
    const unsigned b_base = tiles + A_TOTAL;
    const unsigned mbA  = smem_base + 8;
    const unsigned mbCP = smem_base + 16;                 // +16, +24
    const unsigned mbC0 = smem_base + 32;                 // 8 barriers
    unsigned long long* sBest = (unsigned long long*)(smem + 1024);  // 128 x u64

    const int tid  = threadIdx.x;
    const int wid  = tid >> 5;
    const int lane = tid & 31;
    const int p0   = blockIdx.x * BP;

    if (tid == 0) {
        MBARRIER_INIT(mbA, 1);
        MBARRIER_INIT(mbCP, 1);  MBARRIER_INIT(mbCP + 8, 1);
#pragma unroll
        for (int c = 0; c < NCHUNKS; c++) MBARRIER_INIT(mbC0 + 8u * c, 1);
    }
    if (tid < 128) sBest[tid] = 0ull;
    if (wid == 8) TCGEN05_ALLOC(smem_base, 512);
    __syncthreads();
    unsigned tmem_base;
    asm volatile("ld.shared.b32 %0, [%1];" : "=r"(tmem_base) : "r"(smem_base));

    if (wid == 8) {
        // ------------------- Driver (lane 0 of warp 8) -------------------
        if (lane == 0) {
            auto issue_copyB = [&](int c) {
                const unsigned mb = mbCP + 8u * (unsigned)(c & 1);
                const unsigned dslot = b_base + (unsigned)((c & 1) * B_SLOT_BYTES);
                MBARRIER_EXPECT_TX(mb, 49152u);
#pragma unroll
                for (int s = 0; s < 3; s++) {
#pragma unroll
                    for (int h = 0; h < 2; h++) {
                        const unsigned* src = g_centB + (size_t)s * 32768
                                              + (size_t)h * 16384 + (size_t)c * 2048;
                        unsigned dst = dslot + (unsigned)(s * B_SPLIT_BYTES + h * 8192);
                        BULK_G2S(dst, src, 8192u, mb);
                    }
                }
            };
            auto issue_chunk = [&](int c) {
                const int PA[5] = {0, 1, 1, 0, 2};   // (h,l)(l,h)(l,l)(h,r)(r,h)
                const int PB[5] = {1, 0, 1, 2, 0};
                const unsigned d_t = tmem_base + (unsigned)(64 * c);
                const unsigned bslot = b_base + (unsigned)((c & 1) * B_SLOT_BYTES);
                unsigned en = 0;
#pragma unroll
                for (int sub = 0; sub < KSUB; sub++) {
#pragma unroll
                    for (int ks = 0; ks < 4; ks++) {
                        const unsigned ko  = (unsigned)(sub * 16384 + ks * 32);
                        const unsigned kob = (unsigned)(sub * 8192 + ks * 32);
#pragma unroll
                        for (int p = 0; p < 5; p++) {
                            mma_bf16_ss(d_t,
                                        mk_desc(a_base + PA[p] * A_SPLIT_BYTES + ko),
                                        mk_desc(bslot + PB[p] * B_SPLIT_BYTES + kob),
                                        en);
                            en = 1;
                        }
                    }
                }
#pragma unroll
                for (int sub = 0; sub < KSUB; sub++) {
#pragma unroll
                    for (int ks = 0; ks < 4; ks++) {
                        const unsigned ko  = (unsigned)(sub * 16384 + ks * 32);
                        const unsigned kob = (unsigned)(sub * 8192 + ks * 32);
                        mma_bf16_ss(d_t, mk_desc(a_base + ko),
                                    mk_desc(bslot + kob), 1);
                    }
                }
                TCGEN05_COMMIT(mbC0 + 8u * (unsigned)c);
            };

            MBARRIER_EXPECT_TX(mbA, 98304u);
            BULK_G2S(a_base, g_embA + (size_t)blockIdx.x * A_TILE_U32, 98304u, mbA);
            issue_copyB(0);
            issue_copyB(1);
            MBARRIER_WAIT_PARITY(mbA, 0);
            for (int c = 0; c < NCHUNKS; c++) {
                if (c >= 2) {
                    MBARRIER_WAIT_PARITY(mbC0 + 8u * (unsigned)(c - 2), 0);
                    issue_copyB(c);
                }
                MBARRIER_WAIT_PARITY(mbCP + 8u * (unsigned)(c & 1), (c >> 1) & 1);
                issue_chunk(c);
            }
        }
    } else {
        // --------- Epilogue warps: group g covers chunks 4g..4g+3 ---------
        const int grp = wid >> 2;            // 0 or 1
        const int row = (wid & 3) * 32 + lane;
        float best = -3.402823466e38f;
        int   bidx = 0;
        unsigned rg[32];
        for (int cc = 0; cc < 4; cc++) {
            const int c = grp * 4 + cc;
            MBARRIER_WAIT_PARITY(mbC0 + 8u * (unsigned)c, 0);
            TCGEN05_FENCE_AFTER();
#pragma unroll
            for (int half = 0; half < 2; half++) {
                TCGEN05_LD_32X32B_X32(rg, tmem_base + (unsigned)(64 * c + 32 * half));
                TCGEN05_WAIT_LD();
#pragma unroll
                for (int j = 0; j < 32; j++) {
                    float v = __uint_as_float(rg[j]);
                    int idx = 64 * c + 32 * half + j;
                    if (v > best) { best = v; bidx = idx; }
                }
            }
        }
        TCGEN05_FENCE_BEFORE();
        unsigned long long key =
            ((unsigned long long)f2sortable(best) << 32) | (unsigned)(511 - bidx);
        atomicMax(&sBest[row], key);
    }

    __syncthreads();
    if (tid < 128)
        g_assign[p0 + tid] = 511 - (int)(sBest[tid] & 0xFFFFu);

    // ---- Fused M-step accumulate: all 9 warps, one point per warp pass ----
    for (int pt = wid; pt < BP; pt += 9) {
        int a = 511 - (int)(sBest[pt] & 0xFFFFu);
        float4 v = emb[(size_t)(p0 + pt) * D4 + lane];
        float* dst = g_sums + (size_t)a * D + lane * 4;
        asm volatile("red.global.add.v4.f32 [%0], {%1,%2,%3,%4};"
                     :: "l"(dst), "f"(v.x), "f"(v.y), "f"(v.z), "f"(v.w)
                     : "memory");
        if (lane == 0) atomicAdd(&g_counts[a], 1.0f);
    }

    __syncthreads();
    if (tid == 0) {
        MBARRIER_INVAL(mbA);
        MBARRIER_INVAL(mbCP);  MBARRIER_INVAL(mbCP + 8);
#pragma unroll
        for (int c = 0; c < NCHUNKS; c++) MBARRIER_INVAL(mbC0 + 8u * c);
    }
    __syncthreads();
    if (wid == 8) {
        TCGEN05_RELINQUISH();
        TCGEN05_DEALLOC(tmem_base, 512);
    }
#else
    // ---------------- SIMT fp32 fallback (non-'a' compile pass) ----------------
    const int tid = threadIdx.x;
    const int lane = tid & 31;
    const int wid = tid >> 5;
    const int p0 = blockIdx.x * BP;
    if (tid < 128) {
        const int p = p0 + tid;
        const float4* er = emb + (size_t)p * D4;
        const float4* cb = (const float4*)g_cent;
        float best = -3.402823466e38f;
        int   bidx = 0;
        for (int k = 0; k < K; k++) {
            const float4* cr = cb + (size_t)k * D4;
            float acc = 0.0f;
#pragma unroll 8
            for (int q = 0; q < D4; q++) {
                float4 e = er[q], c4 = cr[q];
                acc += e.x * c4.x; acc += e.y * c4.y;
                acc += e.z * c4.z; acc += e.w * c4.w;
            }
            if (acc > best) { best = acc; bidx = k; }
        }
        g_assign[p] = bidx;
    }
    __syncthreads();
    for (int pt = wid; pt < BP; pt += 9) {
        int a = g_assign[p0 + pt];
        float4 v = emb[(size_t)(p0 + pt) * D4 + lane];
        float* dst = g_sums + (size_t)a * D + lane * 4;
        asm volatile("red.global.add.v4.f32 [%0], {%1,%2,%3,%4};"
                     :: "l"(dst), "f"(v.x), "f"(v.y), "f"(v.z), "f"(v.w)
                     : "memory");
        if (lane == 0) atomicAdd(&g_counts[a], 1.0f);
    }
#endif
}

// ---------------------------------------------------------------------------
// M-step finalize: mean-or-keep, normalize, zero scratch, AND emit the bf16
// split image for the next iteration (folds cent_split into update).
// ---------------------------------------------------------------------------
__global__ void update_kernel() {
    int k = blockIdx.x;
    int d = threadIdx.x;
    float cnt = g_counts[k];
    float s   = g_sums[(size_t)k * D + d];
    float old = g_cent[(size_t)k * D + d];
    float val = (cnt > 0.0f) ? (s / fmaxf(cnt, 1.0f)) : old;

    float sq = val * val;
#pragma unroll
    for (int off = 16; off > 0; off >>= 1)
        sq += __shfl_xor_sync(0xffffffffu, sq, off);

    __shared__ float wsum[4];
    int warp = d >> 5, lane = d & 31;
    if (lane == 0) wsum[warp] = sq;
    __syncthreads();
    float tot = wsum[0] + wsum[1] + wsum[2] + wsum[3];
    float nrm = fmaxf(sqrtf(tot), 1e-12f);

    float nval = val / nrm;
    g_cent[(size_t)k * D + d] = nval;
    g_sums[(size_t)k * D + d] = 0.0f;
    if (d == 0) g_counts[k] = 0.0f;

    // Emit split image: even threads pack (nval, nval_next)
    float nnext = __shfl_down_sync(0xffffffffu, nval, 1);
    if ((d & 1) == 0) {
        unsigned ph, pl, pr;
        split3_pack(nval, nnext, ph, pl, pr);
        unsigned sub = (unsigned)(d >> 6);            // elements 0-63 vs 64-127
        unsigned jp  = (unsigned)((d & 63) >> 1);     // pair index within sub
        unsigned off = (unsigned)(k * 128 + 4 * jp);
        unsigned sw  = SW128(off) >> 2;
        unsigned base = sub * 16384u;
        g_centB[base + sw]           = ph;
        g_centB[32768u + base + sw]  = pl;
        g_centB[65536u + base + sw]  = pr;
    }
}

// ---------------------------------------------------------------------------
__global__ void out_concat_f32(float* __restrict__ out) {
    int i = blockIdx.x * blockDim.x + threadIdx.x;
    if (i < N_PTS) out[i] = (float)g_assign[i];
    if (i < K * D) out[N_PTS + i] = g_cent[i];
}
__global__ void out_assign_i32(int* __restrict__ out) {
    int i = blockIdx.x * blockDim.x + threadIdx.x;
    if (i < N_PTS) out[i] = g_assign[i];
}
__global__ void out_cent_f32(float* __restrict__ out) {
    int i = blockIdx.x * blockDim.x + threadIdx.x;
    if (i < K * D) out[i] = g_cent[i];
}

// ---------------------------------------------------------------------------
extern "C" void kernel_launch(void* const* d_in, const int* in_sizes, int n_in,
                              void* d_out, int out_size) {
    const float* emb   = (const float*)d_in[0];
    const float* initc = (const float*)d_in[1];
    if (n_in >= 2 && in_sizes[0] == K * D && in_sizes[1] == N_PTS * D) {
        const float* tmp = emb; emb = initc; initc = tmp;
    }

    cudaFuncSetAttribute(assign_tc_kernel,
                         cudaFuncAttributeMaxDynamicSharedMemorySize, SMEM_DYN_BYTES);

    init_kernel<<<(K * D + 255) / 256, 256>>>(initc);
    emb_split_kernel<<<NTILE, 256>>>((const float4*)emb);
    cent_split_kernel<<<64, 256>>>();   // image for iteration 0

    for (int it = 0; it < NITER; it++) {
        assign_tc_kernel<<<N_PTS / BP, NTHREADS, SMEM_DYN_BYTES>>>((const float4*)emb);
        update_kernel<<<K, D>>>();      // also emits next iteration's image
    }

    if (out_size == N_PTS) {
        out_assign_i32<<<N_PTS / 256, 256>>>((int*)d_out);
    } else if (out_size == K * D) {
        out_cent_f32<<<(K * D) / 256, 256>>>((float*)d_out);
    } else {
        out_concat_f32<<<(N_PTS + 255) / 256, 256>>>((float*)d_out);
    }
}

// round 15
// speedup vs baseline: 1.1108x; 1.1108x over previous
#include <cuda_runtime.h>
#include <cuda_bf16.h>
#include <cstdint>

// Problem constants
#define N_PTS 262144
#define D     128
#define D4    32
#define K     512
#define NITER 5
#define NTILE (N_PTS / 128)

#define BP        128
#define NCHUNKS   8
#define KSUB      2
#define NTHREADS  288     // warps 0-7 epilogue, warp 8 driver

// SMEM layout
#define A_SPLIT_BYTES  32768
#define A_TOTAL        (3 * A_SPLIT_BYTES)            // 98304
#define B_SPLIT_BYTES  16384
#define B_SLOT_BYTES   (3 * B_SPLIT_BYTES)            // 49152
#define B_TOTAL        (2 * B_SLOT_BYTES)             // 98304
#define SMEM_DYN_BYTES (3072 + A_TOTAL + B_TOTAL)     // 199680

#define A_TILE_U32  24576
#define B_IMG_U32   98304

// bf16 MMA idesc: dtype=F32, a=BF16, b=BF16, N=64, M=128
#define MMA_IDESC 0x08100490u
#define SMEM_DESC_BASE 0x4000404000010000ULL
#define SW128(o) ((o) ^ ((((unsigned)(o)) >> 3) & 0x70u))

#if defined(__CUDA_ARCH__) && (defined(__CUDA_ARCH_FEAT_SM103_ALL) || \
                               defined(__CUDA_ARCH_FEAT_SM100_ALL) || \
                               defined(__CUDA_ARCH_FEAT_SM101_ALL))
#define HAVE_TCGEN05 1
#else
#define HAVE_TCGEN05 0
#endif

// Scratch state
__device__ float    g_cent[K * D];
__device__ float    g_sums[K * D];
__device__ float    g_counts[K];
__device__ int      g_assign[N_PTS];
__device__ __align__(128) unsigned g_embA[NTILE * A_TILE_U32];
__device__ __align__(128) unsigned g_centB[B_IMG_U32];

// ---------------------------------------------------------------------------
__device__ __forceinline__ unsigned smem_u32(const void* p) {
    unsigned a;
    asm("{ .reg .u64 t; cvta.to.shared.u64 t, %1; cvt.u32.u64 %0, t; }"
        : "=r"(a) : "l"(p));
    return a;
}

#define MBARRIER_INIT(a, c) \
    asm volatile("mbarrier.init.shared.b64 [%0], %1;" :: "r"(a), "r"(c) : "memory")
#define MBARRIER_INVAL(a) \
    asm volatile("mbarrier.inval.shared.b64 [%0];" :: "r"(a) : "memory")
#define MBARRIER_EXPECT_TX(a, b) \
    asm volatile("mbarrier.arrive.expect_tx.shared.b64 _, [%0], %1;" \
                 :: "r"(a), "r"(b) : "memory")

#define MBARRIER_WAIT_PARITY(mbar, parity) do { \
    unsigned _m = (mbar), _p = (parity), _d; \
    asm volatile("{\n\t.reg .pred p;\n\t" \
        "mbarrier.try_wait.parity.acquire.cta.shared::cta.b64 p, [%1], %2;\n\t" \
        "selp.b32 %0, 1, 0, p;\n\t}" : "=r"(_d) : "r"(_m), "r"(_p) : "memory"); \
    if (!_d) { \
        asm volatile("{\n\t.reg .pred P1;\n\t" \
            "WL_%=:\n\t" \
            "mbarrier.try_wait.parity.acquire.cta.shared::cta.b64 P1, [%0], %1, 0x989680;\n\t" \
            "@P1 bra.uni WD_%=;\n\tbra.uni WL_%=;\n\tWD_%=:\n\t}" \
            :: "r"(_m), "r"(_p) : "memory"); \
    } \
} while (0)

#define BULK_G2S(dst, src, bytes, mbar) \
    asm volatile("cp.async.bulk.shared::cta.global.mbarrier::complete_tx::bytes " \
                 "[%0], [%1], %2, [%3];" \
                 :: "r"(dst), "l"(src), "r"(bytes), "r"(mbar) : "memory")

#if HAVE_TCGEN05
#define TCGEN05_ALLOC(sa, n) \
    asm volatile("tcgen05.alloc.cta_group::1.sync.aligned.shared::cta.b32 [%0], %1;" \
                 :: "r"(sa), "r"(n) : "memory")
#define TCGEN05_DEALLOC(t, n) \
    asm volatile("tcgen05.dealloc.cta_group::1.sync.aligned.b32 %0, %1;" :: "r"(t), "r"(n))
#define TCGEN05_RELINQUISH() \
    asm volatile("tcgen05.relinquish_alloc_permit.cta_group::1.sync.aligned;")
#define TCGEN05_COMMIT(m) \
    asm volatile("tcgen05.commit.cta_group::1.mbarrier::arrive::one.shared::cluster.b64 [%0];" \
                 :: "r"(m) : "memory")
#define TCGEN05_FENCE_BEFORE() asm volatile("tcgen05.fence::before_thread_sync;" ::: "memory")
#define TCGEN05_FENCE_AFTER()  asm volatile("tcgen05.fence::after_thread_sync;"  ::: "memory")
#define TCGEN05_WAIT_LD()      asm volatile("tcgen05.wait::ld.sync.aligned;" ::: "memory")

#define TCGEN05_LD_32X32B_X32(r, tmem_addr) \
    asm volatile( \
        "tcgen05.ld.sync.aligned.32x32b.x32.b32 " \
        "{%0, %1, %2, %3, %4, %5, %6, %7, " \
        " %8, %9, %10, %11, %12, %13, %14, %15, " \
        " %16, %17, %18, %19, %20, %21, %22, %23, " \
        " %24, %25, %26, %27, %28, %29, %30, %31}, [%32];" \
        : "=r"((r)[0]),  "=r"((r)[1]),  "=r"((r)[2]),  "=r"((r)[3]), \
          "=r"((r)[4]),  "=r"((r)[5]),  "=r"((r)[6]),  "=r"((r)[7]), \
          "=r"((r)[8]),  "=r"((r)[9]),  "=r"((r)[10]), "=r"((r)[11]), \
          "=r"((r)[12]), "=r"((r)[13]), "=r"((r)[14]), "=r"((r)[15]), \
          "=r"((r)[16]), "=r"((r)[17]), "=r"((r)[18]), "=r"((r)[19]), \
          "=r"((r)[20]), "=r"((r)[21]), "=r"((r)[22]), "=r"((r)[23]), \
          "=r"((r)[24]), "=r"((r)[25]), "=r"((r)[26]), "=r"((r)[27]), \
          "=r"((r)[28]), "=r"((r)[29]), "=r"((r)[30]), "=r"((r)[31]) \
        : "r"(tmem_addr))

__device__ __forceinline__ void mma_bf16_ss(unsigned d_tmem, unsigned long long a_desc,
                                            unsigned long long b_desc, unsigned en) {
    asm volatile(
        "{\n\t.reg .pred p;\n\tsetp.ne.u32 p, %4, 0;\n\t"
        "tcgen05.mma.cta_group::1.kind::f16 [%0], %1, %2, %3, {%5, %5, %5, %5}, p;\n\t}"
        :: "r"(d_tmem), "l"(a_desc), "l"(b_desc), "r"(MMA_IDESC), "r"(en), "r"(0u)
        : "memory");
}
#endif  // HAVE_TCGEN05

__device__ __forceinline__ unsigned long long mk_desc(unsigned byte_addr) {
    return SMEM_DESC_BASE | (unsigned long long)((byte_addr >> 4) & 0x3FFFu);
}

__device__ __forceinline__ void split3_pack(float x, float y,
                                            unsigned& ph, unsigned& pl, unsigned& pr) {
    __nv_bfloat16 xh = __float2bfloat16_rn(x);
    float xr1 = x - __bfloat162float(xh);
    __nv_bfloat16 xl = __float2bfloat16_rn(xr1);
    __nv_bfloat16 xr = __float2bfloat16_rn(xr1 - __bfloat162float(xl));
    __nv_bfloat16 yh = __float2bfloat16_rn(y);
    float yr1 = y - __bfloat162float(yh);
    __nv_bfloat16 yl = __float2bfloat16_rn(yr1);
    __nv_bfloat16 yr = __float2bfloat16_rn(yr1 - __bfloat162float(yl));
    ph = (unsigned)__bfloat16_as_ushort(xh) | ((unsigned)__bfloat16_as_ushort(yh) << 16);
    pl = (unsigned)__bfloat16_as_ushort(xl) | ((unsigned)__bfloat16_as_ushort(yl) << 16);
    pr = (unsigned)__bfloat16_as_ushort(xr) | ((unsigned)__bfloat16_as_ushort(yr) << 16);
}

__device__ __forceinline__ unsigned f2sortable(float f) {
    unsigned u = __float_as_uint(f);
    return u ^ (((int)u >> 31) | 0x80000000u);
}

// ---------------------------------------------------------------------------
__global__ void init_kernel(const float* __restrict__ initc) {
    int i = blockIdx.x * blockDim.x + threadIdx.x;
    if (i < K * D) { g_cent[i] = initc[i]; g_sums[i] = 0.0f; }
    if (i < K)     g_counts[i] = 0.0f;
}

// ---------------------------------------------------------------------------
// Once per launch: pack embedding 3-way bf16 splits into swizzled tile images.
// ---------------------------------------------------------------------------
__global__ void emb_split_kernel(const float4* __restrict__ emb) {
    const int tile = blockIdx.x;
    const int w    = threadIdx.x >> 5;
    const int lane = threadIdx.x & 31;
    unsigned* out = g_embA + (size_t)tile * A_TILE_U32;
    const unsigned subbase = (unsigned)(lane >> 4) * 4096u;
    for (int r = w; r < 128; r += 8) {
        float4 v = emb[(size_t)(tile * 128 + r) * D4 + lane];
        unsigned off = (unsigned)(r * 128 + 8 * (lane & 15));
        unsigned s0 = SW128(off) >> 2, s1 = SW128(off + 4) >> 2;
        unsigned ph, pl, pr, qh, ql, qr;
        split3_pack(v.x, v.y, ph, pl, pr);
        split3_pack(v.z, v.w, qh, ql, qr);
        out[subbase + s0]          = ph;  out[subbase + s1]          = qh;
        out[8192u + subbase + s0]  = pl;  out[8192u + subbase + s1]  = ql;
        out[16384u + subbase + s0] = pr;  out[16384u + subbase + s1] = qr;
    }
}

// ---------------------------------------------------------------------------
// Run ONCE before the loop (image for iteration 0); later images come from
// update_kernel's folded emitter.
// ---------------------------------------------------------------------------
__global__ void cent_split_kernel() {
    const int gw   = (blockIdx.x * blockDim.x + threadIdx.x) >> 5;
    const int lane = threadIdx.x & 31;
    if (gw >= K) return;
    float4 v = ((const float4*)g_cent)[(size_t)gw * D4 + lane];
    const unsigned subbase = (unsigned)(lane >> 4) * 16384u;
    unsigned off = (unsigned)(gw * 128 + 8 * (lane & 15));
    unsigned s0 = SW128(off) >> 2, s1 = SW128(off + 4) >> 2;
    unsigned ph, pl, pr, qh, ql, qr;
    split3_pack(v.x, v.y, ph, pl, pr);
    split3_pack(v.z, v.w, qh, ql, qr);
    g_centB[subbase + s0]           = ph;  g_centB[subbase + s1]           = qh;
    g_centB[32768u + subbase + s0]  = pl;  g_centB[32768u + subbase + s1]  = ql;
    g_centB[65536u + subbase + s0]  = pr;  g_centB[65536u + subbase + s1]  = qr;
}

// ---------------------------------------------------------------------------
// E-step, sm_103a — byte-identical compute/sync structure to the round-12
// kernel (best measured): SS tcgen05, single accumulator, smalls-first, 8
// single-use commit barriers, warp-8 driver, overlapped per-chunk epilogue.
// No fused accumulate (round-14 regression).
// ---------------------------------------------------------------------------
__global__ void __launch_bounds__(NTHREADS, 1)
assign_tc_kernel(const float4* __restrict__ emb) {
#if HAVE_TCGEN05
    extern __shared__ char smem[];
    const unsigned smem_base = smem_u32(smem);
    const unsigned tiles = (smem_base + 2048u + 1023u) & ~1023u;
    const unsigned a_base = tiles;
    const unsigned b_base = tiles + A_TOTAL;
    const unsigned mbA  = smem_base + 8;
    const unsigned mbCP = smem_base + 16;                 // +16, +24
    const unsigned mbC0 = smem_base + 32;                 // 8 barriers
    unsigned long long* sBest = (unsigned long long*)(smem + 1024);  // 128 x u64

    const int tid  = threadIdx.x;
    const int wid  = tid >> 5;
    const int lane = tid & 31;
    const int p0   = blockIdx.x * BP;

    if (tid == 0) {
        MBARRIER_INIT(mbA, 1);
        MBARRIER_INIT(mbCP, 1);  MBARRIER_INIT(mbCP + 8, 1);
#pragma unroll
        for (int c = 0; c < NCHUNKS; c++) MBARRIER_INIT(mbC0 + 8u * c, 1);
    }
    if (tid < 128) sBest[tid] = 0ull;
    if (wid == 8) TCGEN05_ALLOC(smem_base, 512);
    __syncthreads();
    unsigned tmem_base;
    asm volatile("ld.shared.b32 %0, [%1];" : "=r"(tmem_base) : "r"(smem_base));

    if (wid == 8) {
        // ------------------- Driver (lane 0 of warp 8) -------------------
        if (lane == 0) {
            auto issue_copyB = [&](int c) {
                const unsigned mb = mbCP + 8u * (unsigned)(c & 1);
                const unsigned dslot = b_base + (unsigned)((c & 1) * B_SLOT_BYTES);
                MBARRIER_EXPECT_TX(mb, 49152u);
#pragma unroll
                for (int s = 0; s < 3; s++) {
#pragma unroll
                    for (int h = 0; h < 2; h++) {
                        const unsigned* src = g_centB + (size_t)s * 32768
                                              + (size_t)h * 16384 + (size_t)c * 2048;
                        unsigned dst = dslot + (unsigned)(s * B_SPLIT_BYTES + h * 8192);
                        BULK_G2S(dst, src, 8192u, mb);
                    }
                }
            };
            auto issue_chunk = [&](int c) {
                const int PA[5] = {0, 1, 1, 0, 2};   // (h,l)(l,h)(l,l)(h,r)(r,h)
                const int PB[5] = {1, 0, 1, 2, 0};
                const unsigned d_t = tmem_base + (unsigned)(64 * c);
                const unsigned bslot = b_base + (unsigned)((c & 1) * B_SLOT_BYTES);
                unsigned en = 0;
#pragma unroll
                for (int sub = 0; sub < KSUB; sub++) {
#pragma unroll
                    for (int ks = 0; ks < 4; ks++) {
                        const unsigned ko  = (unsigned)(sub * 16384 + ks * 32);
                        const unsigned kob = (unsigned)(sub * 8192 + ks * 32);
#pragma unroll
                        for (int p = 0; p < 5; p++) {
                            mma_bf16_ss(d_t,
                                        mk_desc(a_base + PA[p] * A_SPLIT_BYTES + ko),
                                        mk_desc(bslot + PB[p] * B_SPLIT_BYTES + kob),
                                        en);
                            en = 1;
                        }
                    }
                }
#pragma unroll
                for (int sub = 0; sub < KSUB; sub++) {
#pragma unroll
                    for (int ks = 0; ks < 4; ks++) {
                        const unsigned ko  = (unsigned)(sub * 16384 + ks * 32);
                        const unsigned kob = (unsigned)(sub * 8192 + ks * 32);
                        mma_bf16_ss(d_t, mk_desc(a_base + ko),
                                    mk_desc(bslot + kob), 1);
                    }
                }
                TCGEN05_COMMIT(mbC0 + 8u * (unsigned)c);
            };

            MBARRIER_EXPECT_TX(mbA, 98304u);
            BULK_G2S(a_base, g_embA + (size_t)blockIdx.x * A_TILE_U32, 98304u, mbA);
            issue_copyB(0);
            issue_copyB(1);
            MBARRIER_WAIT_PARITY(mbA, 0);
            for (int c = 0; c < NCHUNKS; c++) {
                if (c >= 2) {
                    MBARRIER_WAIT_PARITY(mbC0 + 8u * (unsigned)(c - 2), 0);
                    issue_copyB(c);
                }
                MBARRIER_WAIT_PARITY(mbCP + 8u * (unsigned)(c & 1), (c >> 1) & 1);
                issue_chunk(c);
            }
        }
    } else {
        // --------- Epilogue warps: group g covers chunks 4g..4g+3 ---------
        const int grp = wid >> 2;            // 0 or 1
        const int row = (wid & 3) * 32 + lane;
        float best = -3.402823466e38f;
        int   bidx = 0;
        unsigned rg[32];
        for (int cc = 0; cc < 4; cc++) {
            const int c = grp * 4 + cc;
            MBARRIER_WAIT_PARITY(mbC0 + 8u * (unsigned)c, 0);
            TCGEN05_FENCE_AFTER();
#pragma unroll
            for (int half = 0; half < 2; half++) {
                TCGEN05_LD_32X32B_X32(rg, tmem_base + (unsigned)(64 * c + 32 * half));
                TCGEN05_WAIT_LD();
#pragma unroll
                for (int j = 0; j < 32; j++) {
                    float v = __uint_as_float(rg[j]);
                    int idx = 64 * c + 32 * half + j;
                    if (v > best) { best = v; bidx = idx; }
                }
            }
        }
        TCGEN05_FENCE_BEFORE();
        unsigned long long key =
            ((unsigned long long)f2sortable(best) << 32) | (unsigned)(511 - bidx);
        atomicMax(&sBest[row], key);
    }

    __syncthreads();
    if (tid < 128)
        g_assign[p0 + tid] = 511 - (int)(sBest[tid] & 0xFFFFu);

    __syncthreads();
    if (tid == 0) {
        MBARRIER_INVAL(mbA);
        MBARRIER_INVAL(mbCP);  MBARRIER_INVAL(mbCP + 8);
#pragma unroll
        for (int c = 0; c < NCHUNKS; c++) MBARRIER_INVAL(mbC0 + 8u * c);
    }
    __syncthreads();
    if (wid == 8) {
        TCGEN05_RELINQUISH();
        TCGEN05_DEALLOC(tmem_base, 512);
    }
#else
    // ---------------- SIMT fp32 fallback (non-'a' compile pass) ----------------
    const int tid = threadIdx.x;
    if (tid < 128) {
        const int p = blockIdx.x * BP + tid;
        const float4* er = emb + (size_t)p * D4;
        const float4* cb = (const float4*)g_cent;
        float best = -3.402823466e38f;
        int   bidx = 0;
        for (int k = 0; k < K; k++) {
            const float4* cr = cb + (size_t)k * D4;
            float acc = 0.0f;
#pragma unroll 8
            for (int q = 0; q < D4; q++) {
                float4 e = er[q], c4 = cr[q];
                acc += e.x * c4.x; acc += e.y * c4.y;
                acc += e.z * c4.z; acc += e.w * c4.w;
            }
            if (acc > best) { best = acc; bidx = k; }
        }
        g_assign[p] = bidx;
    }
#endif
}

// ---------------------------------------------------------------------------
// M-step accumulate: one warp per point; vectorized red.add (high occupancy).
// ---------------------------------------------------------------------------
__global__ void accum_kernel(const float4* __restrict__ emb) {
    int gw   = (blockIdx.x * blockDim.x + threadIdx.x) >> 5;
    int lane = threadIdx.x & 31;
    if (gw >= N_PTS) return;
    float4 v = emb[(size_t)gw * D4 + lane];
    int a = g_assign[gw];
    float* dst = g_sums + (size_t)a * D + lane * 4;
    asm volatile("red.global.add.v4.f32 [%0], {%1,%2,%3,%4};"
                 :: "l"(dst), "f"(v.x), "f"(v.y), "f"(v.z), "f"(v.w)
                 : "memory");
    if (lane == 0) atomicAdd(&g_counts[a], 1.0f);
}

// ---------------------------------------------------------------------------
// M-step finalize: mean-or-keep, normalize, zero scratch, AND emit the bf16
// split image for the next iteration (folds cent_split; proven in round 14).
// ---------------------------------------------------------------------------
__global__ void update_kernel() {
    int k = blockIdx.x;
    int d = threadIdx.x;
    float cnt = g_counts[k];
    float s   = g_sums[(size_t)k * D + d];
    float old = g_cent[(size_t)k * D + d];
    float val = (cnt > 0.0f) ? (s / fmaxf(cnt, 1.0f)) : old;

    float sq = val * val;
#pragma unroll
    for (int off = 16; off > 0; off >>= 1)
        sq += __shfl_xor_sync(0xffffffffu, sq, off);

    __shared__ float wsum[4];
    int warp = d >> 5, lane = d & 31;
    if (lane == 0) wsum[warp] = sq;
    __syncthreads();
    float tot = wsum[0] + wsum[1] + wsum[2] + wsum[3];
    float nrm = fmaxf(sqrtf(tot), 1e-12f);

    float nval = val / nrm;
    g_cent[(size_t)k * D + d] = nval;
    g_sums[(size_t)k * D + d] = 0.0f;
    if (d == 0) g_counts[k] = 0.0f;

    // Emit split image: even threads pack (nval, nval_next)
    float nnext = __shfl_down_sync(0xffffffffu, nval, 1);
    if ((d & 1) == 0) {
        unsigned ph, pl, pr;
        split3_pack(nval, nnext, ph, pl, pr);
        unsigned sub = (unsigned)(d >> 6);            // elements 0-63 vs 64-127
        unsigned jp  = (unsigned)((d & 63) >> 1);     // pair index within sub
        unsigned off = (unsigned)(k * 128 + 4 * jp);
        unsigned sw  = SW128(off) >> 2;
        unsigned base = sub * 16384u;
        g_centB[base + sw]           = ph;
        g_centB[32768u + base + sw]  = pl;
        g_centB[65536u + base + sw]  = pr;
    }
}

// ---------------------------------------------------------------------------
__global__ void out_concat_f32(float* __restrict__ out) {
    int i = blockIdx.x * blockDim.x + threadIdx.x;
    if (i < N_PTS) out[i] = (float)g_assign[i];
    if (i < K * D) out[N_PTS + i] = g_cent[i];
}
__global__ void out_assign_i32(int* __restrict__ out) {
    int i = blockIdx.x * blockDim.x + threadIdx.x;
    if (i < N_PTS) out[i] = g_assign[i];
}
__global__ void out_cent_f32(float* __restrict__ out) {
    int i = blockIdx.x * blockDim.x + threadIdx.x;
    if (i < K * D) out[i] = g_cent[i];
}

// ---------------------------------------------------------------------------
extern "C" void kernel_launch(void* const* d_in, const int* in_sizes, int n_in,
                              void* d_out, int out_size) {
    const float* emb   = (const float*)d_in[0];
    const float* initc = (const float*)d_in[1];
    if (n_in >= 2 && in_sizes[0] == K * D && in_sizes[1] == N_PTS * D) {
        const float* tmp = emb; emb = initc; initc = tmp;
    }

    cudaFuncSetAttribute(assign_tc_kernel,
                         cudaFuncAttributeMaxDynamicSharedMemorySize, SMEM_DYN_BYTES);

    init_kernel<<<(K * D + 255) / 256, 256>>>(initc);
    emb_split_kernel<<<NTILE, 256>>>((const float4*)emb);
    cent_split_kernel<<<64, 256>>>();   // image for iteration 0

    for (int it = 0; it < NITER; it++) {
        assign_tc_kernel<<<N_PTS / BP, NTHREADS, SMEM_DYN_BYTES>>>((const float4*)emb);
        accum_kernel<<<(N_PTS * 32) / 256, 256>>>((const float4*)emb);
        update_kernel<<<K, D>>>();      // also emits next iteration's image
    }

    if (out_size == N_PTS) {
        out_assign_i32<<<N_PTS / 256, 256>>>((int*)d_out);
    } else if (out_size == K * D) {
        out_cent_f32<<<(K * D) / 256, 256>>>((float*)d_out);
    } else {
        out_concat_f32<<<(N_PTS + 255) / 256, 256>>>((float*)d_out);
    }
}